// round 2
// baseline (speedup 1.0000x reference)
#include <cuda_runtime.h>

#define N_NODES 50000
#define N_EDGES 800000
#define HDIM 128
#define DDIM 32
#define CDIM 64
#define RDIM 8

// ---- scratch (device globals; no allocation in kernel_launch) ----
__device__ float g_t1[N_NODES * HDIM];          // silu(x)@W1+b1        [N,128]
__device__ float g_hbuf[N_NODES * DDIM];        // h                    [N,32]
__device__ float g_t2[N_NODES * RDIM * HDIM];   // silu(coeffs)@Wc1     [N*R,128]
__device__ float g_cbuf[N_NODES * RDIM * DDIM]; // c                    [N*R,32]
__device__ float g_agg[N_NODES * DDIM];         // segment_sum target   [N,32]

__device__ __forceinline__ float silu_f(float v) { return v / (1.0f + __expf(-v)); }

// Generic fused-silu GEMM: Y[M,NC] = act(A[M,K]) @ W[K,NC] (+bias)
// Block tile: TM rows x NC cols (full N in one block). Per-thread 8x4 register tile.
// blockDim = (NC/4, TM/8).
template<int K, int NC, int TM, bool SILU, bool BIAS>
__global__ void __launch_bounds__((NC/4)*(TM/8)) gemm_silu_kernel(
    const float* __restrict__ A, const float* __restrict__ W,
    const float* __restrict__ bias, float* __restrict__ Y, int M)
{
    __shared__ float As[TM][33];   // +1 pad: conflict-free scalar STS/LDS
    __shared__ float Ws[32][NC];
    const int tx = threadIdx.x;           // 0..NC/4-1
    const int ty = threadIdx.y;           // 0..TM/8-1
    const int TH = (NC/4)*(TM/8);
    const int tid = ty*(NC/4) + tx;
    const int m0 = blockIdx.x * TM;

    float acc[8][4];
#pragma unroll
    for (int i = 0; i < 8; i++)
#pragma unroll
        for (int j = 0; j < 4; j++) acc[i][j] = 0.0f;

    for (int k0 = 0; k0 < K; k0 += 32) {
        // A tile: TM x 32, silu applied at load (each A element loaded by exactly one block)
        for (int idx = tid; idx < TM*8; idx += TH) {
            int row = idx >> 3, cc = idx & 7;
            float4 v = make_float4(0.f, 0.f, 0.f, 0.f);
            int m = m0 + row;
            if (m < M) v = *(const float4*)(A + (size_t)m * K + k0 + cc*4);
            if (SILU) { v.x = silu_f(v.x); v.y = silu_f(v.y); v.z = silu_f(v.z); v.w = silu_f(v.w); }
            As[row][cc*4+0] = v.x; As[row][cc*4+1] = v.y;
            As[row][cc*4+2] = v.z; As[row][cc*4+3] = v.w;
        }
        // W tile: 32 x NC, straight float4 copy
        for (int idx = tid; idx < 8*NC; idx += TH) {
            int kk = idx / (NC/4), cc = idx % (NC/4);
            *(float4*)&Ws[kk][cc*4] = *(const float4*)(W + (size_t)(k0+kk)*NC + cc*4);
        }
        __syncthreads();
#pragma unroll 8
        for (int kk = 0; kk < 32; kk++) {
            float4 w = *(const float4*)&Ws[kk][tx*4];
#pragma unroll
            for (int i = 0; i < 8; i++) {
                float a = As[ty*8+i][kk];   // broadcast within warp
                acc[i][0] = fmaf(a, w.x, acc[i][0]);
                acc[i][1] = fmaf(a, w.y, acc[i][1]);
                acc[i][2] = fmaf(a, w.z, acc[i][2]);
                acc[i][3] = fmaf(a, w.w, acc[i][3]);
            }
        }
        __syncthreads();
    }

    float4 bv = make_float4(0.f, 0.f, 0.f, 0.f);
    if (BIAS) bv = *(const float4*)(bias + tx*4);
#pragma unroll
    for (int i = 0; i < 8; i++) {
        int m = m0 + ty*8 + i;
        if (m < M) {
            float4 o = make_float4(acc[i][0]+bv.x, acc[i][1]+bv.y,
                                   acc[i][2]+bv.z, acc[i][3]+bv.w);
            *(float4*)(Y + (size_t)m * NC + tx*4) = o;
        }
    }
}

// One warp per edge. Lane mapping: lane = r*4 + q ; each lane owns 8 d's (d = q*8..q*8+7).
// ce = c[dst] * (c[src] + 1); per-r l2norm = 2 shfls (over q group);
// r-sum = 3 shfl steps x 8 vals; final w-norm = 2 shfls.
__global__ void edge_kernel(const float* __restrict__ c, const float* __restrict__ h,
                            const float* __restrict__ rbfs, const int* __restrict__ ei,
                            float* __restrict__ agg)
{
    __shared__ float sw[8][32];
    int gwarp = blockIdx.x * 8 + (threadIdx.x >> 5);
    if (gwarp >= N_EDGES) return;
    int lane = threadIdx.x & 31;
    int r = lane >> 2, q = lane & 3;
    int src = ei[gwarp];
    int dst = ei[N_EDGES + gwarp];

    const float4* c4 = (const float4*)c;
    size_t bd = ((size_t)dst * RDIM + r) * 8 + q*2;   // float4 units (row = 32 floats = 8 f4)
    size_t bs = ((size_t)src * RDIM + r) * 8 + q*2;
    float4 d0 = c4[bd], d1 = c4[bd+1];
    float4 s0 = c4[bs], s1 = c4[bs+1];

    float ce[8];
    ce[0] = d0.x * (s0.x + 1.0f); ce[1] = d0.y * (s0.y + 1.0f);
    ce[2] = d0.z * (s0.z + 1.0f); ce[3] = d0.w * (s0.w + 1.0f);
    ce[4] = d1.x * (s1.x + 1.0f); ce[5] = d1.y * (s1.y + 1.0f);
    ce[6] = d1.z * (s1.z + 1.0f); ce[7] = d1.w * (s1.w + 1.0f);

    float ss = 0.f;
#pragma unroll
    for (int i = 0; i < 8; i++) ss = fmaf(ce[i], ce[i], ss);
    ss += __shfl_xor_sync(0xffffffffu, ss, 1);
    ss += __shfl_xor_sync(0xffffffffu, ss, 2);
    float inv = rsqrtf(fmaxf(ss, 1e-24f));            // == 1/max(||v||,1e-12)

    float scale = rbfs[(size_t)gwarp * RDIM + r] * inv;
    float w[8];
#pragma unroll
    for (int i = 0; i < 8; i++) w[i] = ce[i] * scale;

#pragma unroll
    for (int mask = 4; mask <= 16; mask <<= 1)
#pragma unroll
        for (int i = 0; i < 8; i++) w[i] += __shfl_xor_sync(0xffffffffu, w[i], mask);

    float ssw = 0.f;
#pragma unroll
    for (int i = 0; i < 8; i++) ssw = fmaf(w[i], w[i], ssw);
    ssw += __shfl_xor_sync(0xffffffffu, ssw, 1);
    ssw += __shfl_xor_sync(0xffffffffu, ssw, 2);
    float invw = rsqrtf(fmaxf(ssw, 1e-24f));

    int wib = threadIdx.x >> 5;
    if (r == 0) {
#pragma unroll
        for (int i = 0; i < 8; i++) sw[wib][q*8+i] = w[i];
    }
    __syncwarp();
    float wd = sw[wib][lane] * invw;
    float hd = h[(size_t)dst * DDIM + lane];
    atomicAdd(&agg[(size_t)src * DDIM + lane], hd * wd);
}

__global__ void zero_kernel(float4* p, int n4) {
    int i = blockIdx.x * blockDim.x + threadIdx.x;
    if (i < n4) p[i] = make_float4(0.f, 0.f, 0.f, 0.f);
}

extern "C" void kernel_launch(void* const* d_in, const int* in_sizes, int n_in,
                              void* d_out, int out_size)
{
    const float* x      = (const float*)d_in[0];
    const float* rbfs   = (const float*)d_in[1];
    const float* coeffs = (const float*)d_in[2];
    const float* W1     = (const float*)d_in[3];
    const float* b1     = (const float*)d_in[4];
    const float* W2     = (const float*)d_in[5];
    const float* b2     = (const float*)d_in[6];
    const float* Wc1    = (const float*)d_in[7];
    const float* Wc2    = (const float*)d_in[8];
    const float* Wu     = (const float*)d_in[9];
    const int*   ei     = (const int*)d_in[10];
    float* out = (float*)d_out;

    float *t1, *hbuf, *t2, *cbuf, *agg;
    cudaGetSymbolAddress((void**)&t1,   g_t1);
    cudaGetSymbolAddress((void**)&hbuf, g_hbuf);
    cudaGetSymbolAddress((void**)&t2,   g_t2);
    cudaGetSymbolAddress((void**)&cbuf, g_cbuf);
    cudaGetSymbolAddress((void**)&agg,  g_agg);

    // node path: h = silu(silu(x)@W1+b1)@W2+b2
    gemm_silu_kernel<128,128,64,true,true><<<(N_NODES+63)/64, dim3(32,8)>>>(x, W1, b1, t1, N_NODES);
    gemm_silu_kernel<128,32,128,true,true><<<(N_NODES+127)/128, dim3(8,16)>>>(t1, W2, b2, hbuf, N_NODES);

    // coeffs path: c = silu(silu(coeffs)@Wc1)@Wc2   over M = N*R = 400000 rows
    gemm_silu_kernel<64,128,64,true,false><<<(N_NODES*RDIM+63)/64, dim3(32,8)>>>(coeffs, Wc1, nullptr, t2, N_NODES*RDIM);
    gemm_silu_kernel<128,32,128,true,false><<<(N_NODES*RDIM+127)/128, dim3(8,16)>>>(t2, Wc2, nullptr, cbuf, N_NODES*RDIM);

    // zero aggregation buffer
    zero_kernel<<<((N_NODES*DDIM/4) + 255)/256, 256>>>((float4*)agg, N_NODES*DDIM/4);

    // edge stage + atomic segment-sum into agg
    edge_kernel<<<N_EDGES/8, 256>>>(cbuf, hbuf, rbfs, ei, agg);

    // out = agg @ Wu
    gemm_silu_kernel<32,128,64,false,false><<<(N_NODES+63)/64, dim3(32,8)>>>(agg, Wu, nullptr, out, N_NODES);
}